// round 1
// baseline (speedup 1.0000x reference)
#include <cuda_runtime.h>
#include <math.h>

#define S 1024
#define DIN 4096
#define NH 32
#define NG 8
#define HD 128
#define QD 4096   // NH*HD
#define KD 1024   // NG*HD

// Scratch (allocation-free contract: __device__ globals)
__device__ float g_q[S * QD];
__device__ float g_k[S * KD];
__device__ float g_v[S * KD];
__device__ float g_ctx[S * QD];

// ---------------------------------------------------------------------------
// SGEMM: C[M,N] = A[M,K] @ B[K,N], row-major, fp32.
// BM=BN=64, BK=16, 256 threads, 4x4 microtile, float4 everywhere.
// All problem dims here are multiples of 64/16 -> no bounds checks.
// ---------------------------------------------------------------------------
__global__ __launch_bounds__(256) void sgemm_kernel(const float* __restrict__ A,
                                                    const float* __restrict__ B,
                                                    float* __restrict__ C,
                                                    int M, int N, int K)
{
    __shared__ float As[16][68];  // transposed A tile [k][m], padded
    __shared__ float Bs[16][64];  // B tile [k][n]

    const int t  = threadIdx.x;
    const int tc = t & 15;
    const int tr = t >> 4;
    const int bm = blockIdx.y * 64;
    const int bn = blockIdx.x * 64;

    const int arow = t >> 2;          // 0..63
    const int ac4  = (t & 3) * 4;     // 0,4,8,12
    const int brow = t >> 4;          // 0..15
    const int bc4  = (t & 15) * 4;    // 0..60

    const float* Aptr = A + (size_t)(bm + arow) * K + ac4;
    const float* Bptr = B + (size_t)brow * N + bn + bc4;

    float acc[4][4] = {};

    float4 av = *(const float4*)(Aptr);
    float4 bv = *(const float4*)(Bptr);

    for (int k0 = 0; k0 < K; k0 += 16) {
        __syncthreads();
        As[ac4 + 0][arow] = av.x;
        As[ac4 + 1][arow] = av.y;
        As[ac4 + 2][arow] = av.z;
        As[ac4 + 3][arow] = av.w;
        *(float4*)&Bs[brow][bc4] = bv;
        __syncthreads();

        if (k0 + 16 < K) {   // prefetch next tile while computing
            av = *(const float4*)(Aptr + k0 + 16);
            bv = *(const float4*)(Bptr + (size_t)(k0 + 16) * N);
        }

        #pragma unroll
        for (int kk = 0; kk < 16; kk++) {
            float4 a = *(const float4*)&As[kk][tr * 4];
            float4 b = *(const float4*)&Bs[kk][tc * 4];
            float ar[4] = {a.x, a.y, a.z, a.w};
            float br[4] = {b.x, b.y, b.z, b.w};
            #pragma unroll
            for (int i = 0; i < 4; i++)
                #pragma unroll
                for (int j = 0; j < 4; j++)
                    acc[i][j] += ar[i] * br[j];
        }
    }

    #pragma unroll
    for (int i = 0; i < 4; i++) {
        float4 r = make_float4(acc[i][0], acc[i][1], acc[i][2], acc[i][3]);
        *(float4*)&C[(size_t)(bm + tr * 4 + i) * N + bn + tc * 4] = r;
    }
}

// ---------------------------------------------------------------------------
// RoPE (in place). t layout: [S][nh*128]. cos/sin: [S][128], halves duplicated.
// One thread per (s, h, d<64) rotation pair.
// ---------------------------------------------------------------------------
__global__ __launch_bounds__(256) void rope_kernel(float* __restrict__ t,
                                                   const float* __restrict__ cs,
                                                   const float* __restrict__ sn,
                                                   int nh)
{
    int idx = blockIdx.x * blockDim.x + threadIdx.x;
    int d = idx & 63;
    int h = (idx >> 6) % nh;
    int s = idx / (64 * nh);

    float c  = cs[s * HD + d];
    float si = sn[s * HD + d];
    float* row = t + ((size_t)s * nh + h) * HD;
    float t1 = row[d];
    float t2 = row[d + 64];
    row[d]      = t1 * c - t2 * si;
    row[d + 64] = t2 * c + t1 * si;
}

// ---------------------------------------------------------------------------
// Fused causal flash attention, fp32.
// Block = (head h, q-tile qt of 64 rows). 256 threads.
// Microtile: thread (tr=t/16, tc=t%16) owns score rows {tr+16i}, cols {tc+16j},
// and output rows {tr+16i} x cols [tc*8, tc*8+8).
// smem: Qs[64][128], Ks[64][132] (pad), Vs[64][128], Ps[64][65] = 115968 B.
// ---------------------------------------------------------------------------
#define ATTN_SMEM_FLOATS (64*128 + 64*132 + 64*128 + 64*65)
#define ATTN_SMEM_BYTES  (ATTN_SMEM_FLOATS * 4)

__global__ __launch_bounds__(256, 2) void attn_kernel(const float* __restrict__ q,
                                                      const float* __restrict__ k,
                                                      const float* __restrict__ v,
                                                      float* __restrict__ ctx)
{
    extern __shared__ float smf[];
    float* Qs = smf;                         // [64][128]
    float* Ks = Qs + 64 * 128;               // [64][132]
    float* Vs = Ks + 64 * 132;               // [64][128]
    float* Ps = Vs + 64 * 128;               // [64][65]

    const int qt = (int)gridDim.x - 1 - (int)blockIdx.x;  // heavy blocks first
    const int h  = blockIdx.y;
    const int kg = h >> 2;                   // GQA group = h / 4
    const int t  = threadIdx.x;
    const int tc = t & 15;
    const int tr = t >> 4;

    const float* qbase = q + (size_t)(qt * 64) * QD + h * HD;
    const float* kbase = k + (size_t)kg * HD;
    const float* vbase = v + (size_t)kg * HD;

    // Load Q tile (64 x 128)
    for (int it = t; it < 64 * 32; it += 256) {
        int r  = it >> 5;
        int c4 = (it & 31) * 4;
        *(float4*)&Qs[r * 128 + c4] = *(const float4*)(qbase + (size_t)r * QD + c4);
    }

    float m[4], l[4], o[4][8];
    #pragma unroll
    for (int i = 0; i < 4; i++) {
        m[i] = -1e30f;
        l[i] = 0.f;
        #pragma unroll
        for (int c = 0; c < 8; c++) o[i][c] = 0.f;
    }

    const float sc = 0.08838834764831845f;  // 1/sqrt(128)

    for (int kt = 0; kt <= qt; kt++) {
        __syncthreads();  // prev iter's Ks/Vs/Ps readers done
        for (int it = t; it < 64 * 32; it += 256) {
            int r  = it >> 5;
            int c4 = (it & 31) * 4;
            const size_t grow = (size_t)(kt * 64 + r) * KD + c4;
            *(float4*)&Ks[r * 132 + c4] = *(const float4*)(kbase + grow);
            *(float4*)&Vs[r * 128 + c4] = *(const float4*)(vbase + grow);
        }
        __syncthreads();

        // ---- scores s[i][j] = Q[tr+16i] . K[tc+16j] ----
        float s[4][4] = {};
        #pragma unroll 4
        for (int kk = 0; kk < 128; kk += 4) {
            float4 A[4], B[4];
            #pragma unroll
            for (int i = 0; i < 4; i++)
                A[i] = *(const float4*)&Qs[(tr + 16 * i) * 128 + kk];
            #pragma unroll
            for (int j = 0; j < 4; j++)
                B[j] = *(const float4*)&Ks[(tc + 16 * j) * 132 + kk];
            #pragma unroll
            for (int i = 0; i < 4; i++)
                #pragma unroll
                for (int j = 0; j < 4; j++)
                    s[i][j] += A[i].x * B[j].x + A[i].y * B[j].y
                             + A[i].z * B[j].z + A[i].w * B[j].w;
        }

        // ---- mask + scale ----
        const bool diag = (kt == qt);
        #pragma unroll
        for (int i = 0; i < 4; i++)
            #pragma unroll
            for (int j = 0; j < 4; j++) {
                if (diag && (tc + 16 * j) > (tr + 16 * i)) s[i][j] = -1e30f;
                else s[i][j] *= sc;
            }

        // ---- online softmax update ----
        #pragma unroll
        for (int i = 0; i < 4; i++) {
            float mt = fmaxf(fmaxf(s[i][0], s[i][1]), fmaxf(s[i][2], s[i][3]));
            #pragma unroll
            for (int off = 8; off >= 1; off >>= 1)
                mt = fmaxf(mt, __shfl_xor_sync(0xffffffffu, mt, off));
            float mn = fmaxf(m[i], mt);

            float p0 = __expf(s[i][0] - mn);
            float p1 = __expf(s[i][1] - mn);
            float p2 = __expf(s[i][2] - mn);
            float p3 = __expf(s[i][3] - mn);
            const int rr = (tr + 16 * i) * 65;
            Ps[rr + tc     ] = p0;
            Ps[rr + tc + 16] = p1;
            Ps[rr + tc + 32] = p2;
            Ps[rr + tc + 48] = p3;

            float ps = p0 + p1 + p2 + p3;
            #pragma unroll
            for (int off = 8; off >= 1; off >>= 1)
                ps += __shfl_xor_sync(0xffffffffu, ps, off);

            float osc = __expf(m[i] - mn);
            l[i] = l[i] * osc + ps;
            m[i] = mn;
            #pragma unroll
            for (int c = 0; c < 8; c++) o[i][c] *= osc;
        }
        __syncthreads();  // Ps visible

        // ---- O += P @ V ----
        #pragma unroll 4
        for (int j = 0; j < 64; j++) {
            float p0 = Ps[(tr     ) * 65 + j];
            float p1 = Ps[(tr + 16) * 65 + j];
            float p2 = Ps[(tr + 32) * 65 + j];
            float p3 = Ps[(tr + 48) * 65 + j];
            float4 va = *(const float4*)&Vs[j * 128 + tc * 8];
            float4 vb = *(const float4*)&Vs[j * 128 + tc * 8 + 4];
            o[0][0] += p0 * va.x; o[0][1] += p0 * va.y; o[0][2] += p0 * va.z; o[0][3] += p0 * va.w;
            o[0][4] += p0 * vb.x; o[0][5] += p0 * vb.y; o[0][6] += p0 * vb.z; o[0][7] += p0 * vb.w;
            o[1][0] += p1 * va.x; o[1][1] += p1 * va.y; o[1][2] += p1 * va.z; o[1][3] += p1 * va.w;
            o[1][4] += p1 * vb.x; o[1][5] += p1 * vb.y; o[1][6] += p1 * vb.z; o[1][7] += p1 * vb.w;
            o[2][0] += p2 * va.x; o[2][1] += p2 * va.y; o[2][2] += p2 * va.z; o[2][3] += p2 * va.w;
            o[2][4] += p2 * vb.x; o[2][5] += p2 * vb.y; o[2][6] += p2 * vb.z; o[2][7] += p2 * vb.w;
            o[3][0] += p3 * va.x; o[3][1] += p3 * va.y; o[3][2] += p3 * va.z; o[3][3] += p3 * va.w;
            o[3][4] += p3 * vb.x; o[3][5] += p3 * vb.y; o[3][6] += p3 * vb.z; o[3][7] += p3 * vb.w;
        }
        // next-iteration top sync guards Ks/Vs/Ps reuse
    }

    float* cbase = ctx + (size_t)(qt * 64) * QD + h * HD;
    #pragma unroll
    for (int i = 0; i < 4; i++) {
        float il = 1.0f / l[i];
        int r = tr + 16 * i;
        float4 r0 = make_float4(o[i][0] * il, o[i][1] * il, o[i][2] * il, o[i][3] * il);
        float4 r1 = make_float4(o[i][4] * il, o[i][5] * il, o[i][6] * il, o[i][7] * il);
        *(float4*)&cbase[(size_t)r * QD + tc * 8    ] = r0;
        *(float4*)&cbase[(size_t)r * QD + tc * 8 + 4] = r1;
    }
}

// ---------------------------------------------------------------------------
// Launch. Inputs (metadata order): x, mask(unused: causal known), cos, sin,
// Wq, Wk, Wv, Wo. Output: [1,1024,4096] fp32.
// ---------------------------------------------------------------------------
extern "C" void kernel_launch(void* const* d_in, const int* in_sizes, int n_in,
                              void* d_out, int out_size)
{
    (void)in_sizes; (void)n_in; (void)out_size;
    const float* x  = (const float*)d_in[0];
    const float* cs = (const float*)d_in[2];
    const float* sn = (const float*)d_in[3];
    const float* Wq = (const float*)d_in[4];
    const float* Wk = (const float*)d_in[5];
    const float* Wv = (const float*)d_in[6];
    const float* Wo = (const float*)d_in[7];
    float* out = (float*)d_out;

    float *qp, *kp, *vp, *cp;
    cudaGetSymbolAddress((void**)&qp, g_q);
    cudaGetSymbolAddress((void**)&kp, g_k);
    cudaGetSymbolAddress((void**)&vp, g_v);
    cudaGetSymbolAddress((void**)&cp, g_ctx);

    // QKV projections
    dim3 gq(QD / 64, S / 64);
    dim3 gk(KD / 64, S / 64);
    sgemm_kernel<<<gq, 256>>>(x, Wq, qp, S, QD, DIN);
    sgemm_kernel<<<gk, 256>>>(x, Wk, kp, S, KD, DIN);
    sgemm_kernel<<<gk, 256>>>(x, Wv, vp, S, KD, DIN);

    // RoPE on q and k
    rope_kernel<<<(S * NH * 64) / 256, 256>>>(qp, cs, sn, NH);
    rope_kernel<<<(S * NG * 64) / 256, 256>>>(kp, cs, sn, NG);

    // Fused causal attention
    cudaFuncSetAttribute(attn_kernel, cudaFuncAttributeMaxDynamicSharedMemorySize,
                         ATTN_SMEM_BYTES);
    attn_kernel<<<dim3(S / 64, NH), 256, ATTN_SMEM_BYTES>>>(qp, kp, vp, cp);

    // Output projection
    sgemm_kernel<<<gq, 256>>>(cp, Wo, out, S, QD, QD);
}

// round 6
// speedup vs baseline: 1.7220x; 1.7220x over previous
#include <cuda_runtime.h>
#include <cuda_bf16.h>
#include <cstdint>
#include <math.h>

#define S    1024
#define DIN  4096
#define NH   32
#define NG   8
#define HD   128
#define QD   4096   // NH*HD
#define KVD  2048   // packed k|v row stride
#define KTOT 12288  // 3 * 4096 concatenated-K for hi/lo split GEMM

// ---------------------------------------------------------------------------
// Scratch (__device__ globals: allocation-free contract).
// g_xc doubles as the context-split buffer: x's bf16 form is dead once the
// two projection GEMMs have run, and the attention output split happens after.
// ---------------------------------------------------------------------------
__device__ __align__(256) __nv_bfloat16 g_xc[S * KTOT];       // [hi | lo | hi]
__device__ __align__(256) __nv_bfloat16 g_wq[QD * KTOT];      // [hi | hi | lo]
__device__ __align__(256) __nv_bfloat16 g_wkv[KVD * KTOT];
__device__ __align__(256) __nv_bfloat16 g_wo[QD * KTOT];
__device__ __align__(256) float g_q[S * QD];
__device__ __align__(256) float g_kv[S * KVD];  // cols 0..1023 k, 1024..2047 v
__device__ __align__(256) float g_ctx[S * QD];

// ---------------------------------------------------------------------------
// PTX helpers (sm_100-safe: mma.sync / ldmatrix / cp.async only)
// ---------------------------------------------------------------------------
__device__ __forceinline__ uint32_t smem_u32(const void* p) {
    uint32_t a;
    asm("{ .reg .u64 t; cvta.to.shared.u64 t, %1; cvt.u32.u64 %0, t; }"
        : "=r"(a) : "l"(p));
    return a;
}

#define CP_ASYNC16(dst, src) \
    asm volatile("cp.async.cg.shared.global [%0], [%1], 16;" :: "r"(dst), "l"(src))
#define CP_COMMIT() asm volatile("cp.async.commit_group;" ::: "memory")
#define CP_WAIT2()  asm volatile("cp.async.wait_group 2;" ::: "memory")
#define CP_WAIT1()  asm volatile("cp.async.wait_group 1;" ::: "memory")
#define CP_WAIT0()  asm volatile("cp.async.wait_group 0;" ::: "memory")

__device__ __forceinline__ void ldsm4(uint32_t* r, uint32_t addr) {
    asm volatile("ldmatrix.sync.aligned.m8n8.x4.shared.b16 {%0,%1,%2,%3}, [%4];"
                 : "=r"(r[0]), "=r"(r[1]), "=r"(r[2]), "=r"(r[3]) : "r"(addr));
}

__device__ __forceinline__ void mma16816(float* c, const uint32_t* a, const uint32_t* b) {
    asm volatile("mma.sync.aligned.m16n8k16.row.col.f32.bf16.bf16.f32 "
                 "{%0,%1,%2,%3}, {%4,%5,%6,%7}, {%8,%9}, {%0,%1,%2,%3};"
                 : "+f"(c[0]), "+f"(c[1]), "+f"(c[2]), "+f"(c[3])
                 : "r"(a[0]), "r"(a[1]), "r"(a[2]), "r"(a[3]),
                   "r"(b[0]), "r"(b[1]));
}

// ---------------------------------------------------------------------------
// bf16 GEMM via mma.sync: C[M,N] = A'[M,KTOT] @ B'[N,KTOT]^T (both K-major).
// BM=128, BN=256, BK=64, 256 threads. Warp grid 2(M)x4(N): warp tile 64x64.
// smem rows padded to 144B -> conflict-free ldmatrix. 3-stage cp.async.
// ---------------------------------------------------------------------------
#define BM 128
#define BN 256
#define BK 64
#define ASTRIDE 144
#define A_BYTES (BM * ASTRIDE)        // 18432
#define B_BYTES (BN * ASTRIDE)        // 36864
#define STAGE   (A_BYTES + B_BYTES)   // 55296
#define G_SMEM  (3 * STAGE)           // 165888

__global__ __launch_bounds__(256, 1)
void gemm_bf16(const __nv_bfloat16* __restrict__ A,
               const __nv_bfloat16* __restrict__ B,
               float* __restrict__ C, int M, int N)
{
    extern __shared__ __align__(1024) char sm[];
    const uint32_t sb = smem_u32(sm);
    const int t    = threadIdx.x;
    const int wid  = t >> 5;
    const int lane = t & 31;
    const int m0 = blockIdx.y * BM;
    const int n0 = blockIdx.x * BN;
    const int NS = KTOT / BK;          // 192

    const int wm = wid & 1;            // M half (64 rows)
    const int wn = wid >> 1;           // N quarter (64 cols)

    // ---- stage loader: each row = 64 bf16 = 128 B = 8 chunks of 16B ----
    // A: 128 rows * 8 = 1024 chunks; B: 256 rows * 8 = 2048 chunks.
    auto load_stage = [&](int s) {
        const uint32_t base = sb + (uint32_t)(s % 3) * STAGE;
        const __nv_bfloat16* Ag = A + (size_t)m0 * KTOT + s * BK;
        const __nv_bfloat16* Bg = B + (size_t)n0 * KTOT + s * BK;
        #pragma unroll
        for (int u = 0; u < 4; u++) {
            int c = t + u * 256;
            int row = c >> 3, ch = c & 7;
            CP_ASYNC16(base + row * ASTRIDE + ch * 16,
                       Ag + (size_t)row * KTOT + ch * 8);
        }
        #pragma unroll
        for (int u = 0; u < 8; u++) {
            int c = t + u * 256;
            int row = c >> 3, ch = c & 7;
            CP_ASYNC16(base + A_BYTES + row * ASTRIDE + ch * 16,
                       Bg + (size_t)row * KTOT + ch * 8);
        }
        CP_COMMIT();
    };

    load_stage(0);
    load_stage(1);
    load_stage(2);

    float cacc[4][8][4];
    #pragma unroll
    for (int i = 0; i < 4; i++)
        #pragma unroll
        for (int j = 0; j < 8; j++)
            #pragma unroll
            for (int r = 0; r < 4; r++) cacc[i][j][r] = 0.f;

    // ldmatrix lane-address components (constant over k)
    // A: lanes 0-15 -> rows 0-15 at +0B (k0-7); lanes 16-31 -> rows 0-15 at +16B (k8-15)
    const uint32_t aLaneRow = (uint32_t)(wm * 64 + (lane & 15));
    const uint32_t aLaneKof = (uint32_t)((lane >> 4) * 16);
    // B: [n0-7@k0][n0-7@k8][n8-15@k0][n8-15@k8]
    const uint32_t bLaneRow = (uint32_t)(wn * 64 + ((lane >> 4) << 3) + (lane & 7));
    const uint32_t bLaneKof = (uint32_t)(((lane >> 3) & 1) * 16);

    for (int s = 0; s < NS; s++) {
        if (s <= NS - 3)      { CP_WAIT2(); }
        else if (s == NS - 2) { CP_WAIT1(); }
        else                  { CP_WAIT0(); }
        __syncthreads();

        const uint32_t sA = sb + (uint32_t)(s % 3) * STAGE;
        const uint32_t sB = sA + A_BYTES;
        const uint32_t aBase = sA + aLaneRow * ASTRIDE + aLaneKof;
        const uint32_t bBase = sB + bLaneRow * ASTRIDE + bLaneKof;

        #pragma unroll
        for (int kk = 0; kk < 4; kk++) {           // k-step of 16 (32 bytes)
            uint32_t a[4][4];
            #pragma unroll
            for (int mi = 0; mi < 4; mi++)
                ldsm4(a[mi], aBase + (uint32_t)(mi * 16 * ASTRIDE) + kk * 32);
            #pragma unroll
            for (int nj = 0; nj < 4; nj++) {       // 16 n-cols per ldsm4
                uint32_t b[4];
                ldsm4(b, bBase + (uint32_t)(nj * 16 * ASTRIDE) + kk * 32);
                #pragma unroll
                for (int mi = 0; mi < 4; mi++) {
                    mma16816(cacc[mi][2 * nj],     a[mi], b);
                    mma16816(cacc[mi][2 * nj + 1], a[mi], b + 2);
                }
            }
        }

        __syncthreads();
        if (s + 3 < NS) load_stage(s + 3);
    }

    // ---- epilogue ----
    const int g = lane >> 2;
    const int i4 = lane & 3;
    #pragma unroll
    for (int mi = 0; mi < 4; mi++) {
        const int row = m0 + wm * 64 + mi * 16 + g;
        #pragma unroll
        for (int nj = 0; nj < 8; nj++) {
            const int col = n0 + wn * 64 + nj * 8 + 2 * i4;
            float2* p0 = (float2*)(C + (size_t)row * N + col);
            float2* p1 = (float2*)(C + (size_t)(row + 8) * N + col);
            *p0 = make_float2(cacc[mi][nj][0], cacc[mi][nj][1]);
            *p1 = make_float2(cacc[mi][nj][2], cacc[mi][nj][3]);
        }
    }
}

// ---------------------------------------------------------------------------
// Split fp32 [M][4096] -> concatenated bf16 [M][12288] = [hi | lo | hi].
// ---------------------------------------------------------------------------
__global__ __launch_bounds__(256) void split_cat(const float* __restrict__ in,
                                                 __nv_bfloat16* __restrict__ out)
{
    int i = blockIdx.x * 256 + threadIdx.x;        // over M*1024 float4 groups
    int m  = i >> 10;
    int k4 = (i & 1023) * 4;
    float4 v = ((const float4*)in)[i];
    float f[4] = { v.x, v.y, v.z, v.w };
    __nv_bfloat16 h[4], l[4];
    #pragma unroll
    for (int j = 0; j < 4; j++) {
        h[j] = __float2bfloat16(f[j]);
        l[j] = __float2bfloat16(f[j] - __bfloat162float(h[j]));
    }
    __nv_bfloat162 h0(h[0], h[1]), h1(h[2], h[3]);
    __nv_bfloat162 l0(l[0], l[1]), l1(l[2], l[3]);
    __nv_bfloat162* o = (__nv_bfloat162*)(out + (size_t)m * KTOT);
    int p = k4 >> 1;
    o[p] = h0;                 o[p + 1] = h1;                 // hi at [0,4096)
    o[p + 2048] = l0;          o[p + 2049] = l1;              // lo at [4096,8192)
    o[p + 4096] = h0;          o[p + 4097] = h1;              // hi at [8192,12288)
}

// ---------------------------------------------------------------------------
// Transpose + split weights: W [4096][N] fp32 -> B' [rowOff+N][12288] bf16
// with cols [hi | hi | lo].
// ---------------------------------------------------------------------------
__global__ __launch_bounds__(256) void tsplit_cat(const float* __restrict__ W,
                                                  __nv_bfloat16* __restrict__ out,
                                                  int N, int rowOff)
{
    __shared__ float tile[32][33];
    const int n0 = blockIdx.x * 32;
    const int k0 = blockIdx.y * 32;
    const int x = threadIdx.x & 31;
    const int y = threadIdx.x >> 5;
    #pragma unroll
    for (int i = 0; i < 4; i++)
        tile[y + 8 * i][x] = W[(size_t)(k0 + y + 8 * i) * N + n0 + x];
    __syncthreads();
    #pragma unroll
    for (int i = 0; i < 4; i++) {
        int nn = y + 8 * i;
        float f = tile[x][nn];
        __nv_bfloat16 h = __float2bfloat16(f);
        __nv_bfloat16 l = __float2bfloat16(f - __bfloat162float(h));
        size_t o = (size_t)(rowOff + n0 + nn) * KTOT + k0 + x;
        out[o]        = h;
        out[o + 4096] = h;
        out[o + 8192] = l;
    }
}

// ---------------------------------------------------------------------------
// RoPE (in place), row stride parametrized (packed kv buffer for k heads).
// ---------------------------------------------------------------------------
__global__ __launch_bounds__(256) void rope_kernel(float* __restrict__ tptr,
                                                   const float* __restrict__ cs,
                                                   const float* __restrict__ sn,
                                                   int nh, int stride)
{
    int idx = blockIdx.x * blockDim.x + threadIdx.x;
    int d = idx & 63;
    int h = (idx >> 6) % nh;
    int s = idx / (64 * nh);

    float c  = cs[s * HD + d];
    float si = sn[s * HD + d];
    float* row = tptr + (size_t)s * stride + h * HD;
    float t1 = row[d];
    float t2 = row[d + 64];
    row[d]      = t1 * c - t2 * si;
    row[d + 64] = t2 * c + t1 * si;
}

// ---------------------------------------------------------------------------
// Fused causal flash attention, fp32 (kv packed: k at col 0, v at col 1024).
// ---------------------------------------------------------------------------
#define ATTN_SMEM_FLOATS (64*128 + 64*132 + 64*128 + 64*65)
#define ATTN_SMEM_BYTES  (ATTN_SMEM_FLOATS * 4)

__global__ __launch_bounds__(256, 2) void attn_kernel(const float* __restrict__ q,
                                                      const float* __restrict__ kv,
                                                      float* __restrict__ ctx)
{
    extern __shared__ float smf[];
    float* Qs = smf;
    float* Ks = Qs + 64 * 128;
    float* Vs = Ks + 64 * 132;
    float* Ps = Vs + 64 * 128;

    const int qt = (int)gridDim.x - 1 - (int)blockIdx.x;
    const int h  = blockIdx.y;
    const int kg = h >> 2;
    const int t  = threadIdx.x;
    const int tc = t & 15;
    const int tr = t >> 4;

    const float* qbase = q + (size_t)(qt * 64) * QD + h * HD;
    const float* kbase = kv + kg * HD;
    const float* vbase = kv + 1024 + kg * HD;

    for (int it = t; it < 64 * 32; it += 256) {
        int r  = it >> 5;
        int c4 = (it & 31) * 4;
        *(float4*)&Qs[r * 128 + c4] = *(const float4*)(qbase + (size_t)r * QD + c4);
    }

    float m[4], l[4], o[4][8];
    #pragma unroll
    for (int i = 0; i < 4; i++) {
        m[i] = -1e30f;
        l[i] = 0.f;
        #pragma unroll
        for (int c = 0; c < 8; c++) o[i][c] = 0.f;
    }

    const float sc = 0.08838834764831845f;

    for (int kt = 0; kt <= qt; kt++) {
        __syncthreads();
        for (int it = t; it < 64 * 32; it += 256) {
            int r  = it >> 5;
            int c4 = (it & 31) * 4;
            const size_t grow = (size_t)(kt * 64 + r) * KVD + c4;
            *(float4*)&Ks[r * 132 + c4] = *(const float4*)(kbase + grow);
            *(float4*)&Vs[r * 128 + c4] = *(const float4*)(vbase + grow);
        }
        __syncthreads();

        float s[4][4] = {};
        #pragma unroll 4
        for (int kk = 0; kk < 128; kk += 4) {
            float4 A[4], B[4];
            #pragma unroll
            for (int i = 0; i < 4; i++)
                A[i] = *(const float4*)&Qs[(tr + 16 * i) * 128 + kk];
            #pragma unroll
            for (int j = 0; j < 4; j++)
                B[j] = *(const float4*)&Ks[(tc + 16 * j) * 132 + kk];
            #pragma unroll
            for (int i = 0; i < 4; i++)
                #pragma unroll
                for (int j = 0; j < 4; j++)
                    s[i][j] += A[i].x * B[j].x + A[i].y * B[j].y
                             + A[i].z * B[j].z + A[i].w * B[j].w;
        }

        const bool diag = (kt == qt);
        #pragma unroll
        for (int i = 0; i < 4; i++)
            #pragma unroll
            for (int j = 0; j < 4; j++) {
                if (diag && (tc + 16 * j) > (tr + 16 * i)) s[i][j] = -1e30f;
                else s[i][j] *= sc;
            }

        #pragma unroll
        for (int i = 0; i < 4; i++) {
            float mt = fmaxf(fmaxf(s[i][0], s[i][1]), fmaxf(s[i][2], s[i][3]));
            #pragma unroll
            for (int off = 8; off >= 1; off >>= 1)
                mt = fmaxf(mt, __shfl_xor_sync(0xffffffffu, mt, off));
            float mn = fmaxf(m[i], mt);

            float p0 = __expf(s[i][0] - mn);
            float p1 = __expf(s[i][1] - mn);
            float p2 = __expf(s[i][2] - mn);
            float p3 = __expf(s[i][3] - mn);
            const int rr = (tr + 16 * i) * 65;
            Ps[rr + tc     ] = p0;
            Ps[rr + tc + 16] = p1;
            Ps[rr + tc + 32] = p2;
            Ps[rr + tc + 48] = p3;

            float ps = p0 + p1 + p2 + p3;
            #pragma unroll
            for (int off = 8; off >= 1; off >>= 1)
                ps += __shfl_xor_sync(0xffffffffu, ps, off);

            float osc = __expf(m[i] - mn);
            l[i] = l[i] * osc + ps;
            m[i] = mn;
            #pragma unroll
            for (int c = 0; c < 8; c++) o[i][c] *= osc;
        }
        __syncthreads();

        #pragma unroll 4
        for (int j = 0; j < 64; j++) {
            float p0 = Ps[(tr     ) * 65 + j];
            float p1 = Ps[(tr + 16) * 65 + j];
            float p2 = Ps[(tr + 32) * 65 + j];
            float p3 = Ps[(tr + 48) * 65 + j];
            float4 va = *(const float4*)&Vs[j * 128 + tc * 8];
            float4 vb = *(const float4*)&Vs[j * 128 + tc * 8 + 4];
            o[0][0] += p0 * va.x; o[0][1] += p0 * va.y; o[0][2] += p0 * va.z; o[0][3] += p0 * va.w;
            o[0][4] += p0 * vb.x; o[0][5] += p0 * vb.y; o[0][6] += p0 * vb.z; o[0][7] += p0 * vb.w;
            o[1][0] += p1 * va.x; o[1][1] += p1 * va.y; o[1][2] += p1 * va.z; o[1][3] += p1 * va.w;
            o[1][4] += p1 * vb.x; o[1][5] += p1 * vb.y; o[1][6] += p1 * vb.z; o[1][7] += p1 * vb.w;
            o[2][0] += p2 * va.x; o[2][1] += p2 * va.y; o[2][2] += p2 * va.z; o[2][3] += p2 * va.w;
            o[2][4] += p2 * vb.x; o[2][5] += p2 * vb.y; o[2][6] += p2 * vb.z; o[2][7] += p2 * vb.w;
            o[3][0] += p3 * va.x; o[3][1] += p3 * va.y; o[3][2] += p3 * va.z; o[3][3] += p3 * va.w;
            o[3][4] += p3 * vb.x; o[3][5] += p3 * vb.y; o[3][6] += p3 * vb.z; o[3][7] += p3 * vb.w;
        }
    }

    float* cbase = ctx + (size_t)(qt * 64) * QD + h * HD;
    #pragma unroll
    for (int i = 0; i < 4; i++) {
        float il = 1.0f / l[i];
        int r = tr + 16 * i;
        float4 r0 = make_float4(o[i][0] * il, o[i][1] * il, o[i][2] * il, o[i][3] * il);
        float4 r1 = make_float4(o[i][4] * il, o[i][5] * il, o[i][6] * il, o[i][7] * il);
        *(float4*)&cbase[(size_t)r * QD + tc * 8    ] = r0;
        *(float4*)&cbase[(size_t)r * QD + tc * 8 + 4] = r1;
    }
}

// ---------------------------------------------------------------------------
// Launch. Inputs: x, mask(unused), cos, sin, Wq, Wk, Wv, Wo. Output fp32.
// ---------------------------------------------------------------------------
extern "C" void kernel_launch(void* const* d_in, const int* in_sizes, int n_in,
                              void* d_out, int out_size)
{
    (void)in_sizes; (void)n_in; (void)out_size;
    const float* x  = (const float*)d_in[0];
    const float* cs = (const float*)d_in[2];
    const float* sn = (const float*)d_in[3];
    const float* Wq = (const float*)d_in[4];
    const float* Wk = (const float*)d_in[5];
    const float* Wv = (const float*)d_in[6];
    const float* Wo = (const float*)d_in[7];
    float* out = (float*)d_out;

    __nv_bfloat16 *xc, *wq, *wkv, *wo;
    float *qp, *kvp, *cp;
    cudaGetSymbolAddress((void**)&xc,  g_xc);
    cudaGetSymbolAddress((void**)&wq,  g_wq);
    cudaGetSymbolAddress((void**)&wkv, g_wkv);
    cudaGetSymbolAddress((void**)&wo,  g_wo);
    cudaGetSymbolAddress((void**)&qp,  g_q);
    cudaGetSymbolAddress((void**)&kvp, g_kv);
    cudaGetSymbolAddress((void**)&cp,  g_ctx);

    cudaFuncSetAttribute(gemm_bf16, cudaFuncAttributeMaxDynamicSharedMemorySize,
                         G_SMEM);
    cudaFuncSetAttribute(attn_kernel, cudaFuncAttributeMaxDynamicSharedMemorySize,
                         ATTN_SMEM_BYTES);

    // 1. split x -> concatenated bf16
    split_cat<<<S * 1024 / 256, 256>>>(x, xc);

    // 2. transpose + split weights
    tsplit_cat<<<dim3(QD / 32, DIN / 32), 256>>>(Wq, wq, QD, 0);
    tsplit_cat<<<dim3(1024 / 32, DIN / 32), 256>>>(Wk, wkv, 1024, 0);
    tsplit_cat<<<dim3(1024 / 32, DIN / 32), 256>>>(Wv, wkv, 1024, 1024);
    tsplit_cat<<<dim3(QD / 32, QD / 32), 256>>>(Wo, wo, QD, 0);

    // 3. projections (tensor cores via mma.sync)
    gemm_bf16<<<dim3(QD / BN, S / BM), 256, G_SMEM>>>(xc, wq, qp, S, QD);
    gemm_bf16<<<dim3(KVD / BN, S / BM), 256, G_SMEM>>>(xc, wkv, kvp, S, KVD);

    // 4. RoPE
    rope_kernel<<<(S * NH * 64) / 256, 256>>>(qp, cs, sn, NH, QD);
    rope_kernel<<<(S * NG * 64) / 256, 256>>>(kvp, cs, sn, NG, KVD);

    // 5. attention (fp32)
    attn_kernel<<<dim3(S / 64, NH), 256, ATTN_SMEM_BYTES>>>(qp, kvp, cp);

    // 6. out projection (ctx split reuses g_xc)
    split_cat<<<S * 1024 / 256, 256>>>(cp, xc);
    gemm_bf16<<<dim3(QD / BN, S / BM), 256, G_SMEM>>>(xc, wo, out, S, QD);
}